// round 6
// baseline (speedup 1.0000x reference)
#include <cuda_runtime.h>
#include <math.h>
#include <stdint.h>

#define BB   4
#define NN   2048
#define DIMM 1024
#define HID  4096
#define NE   16
#define CAP  256
#define NTOK (BB*NN)          // 8192 tokens
#define NSLOT (NE*BB*CAP)     // 16384 expert slot rows
#define FLT_MIN_NORM 1.17549435e-38f
#define EXP_FTZ_CUT  (-87.336544f)   // exp(x) < min normal below this

// ------------------------- scratch (device globals) -------------------------
__device__ float g_probs[NTOK*NE];          // fp32 softmax probs per token
__device__ int   g_e1[NTOK], g_e2[NTOK];
__device__ float g_g1[NTOK], g_g2[NTOK];    // normalized top1/top2 gates
__device__ int   g_slot1[NTOK], g_slot2[NTOK];  // slot row index or -1
__device__ int   g_slot_token[NSLOT];       // token index or -1
__device__ int   g_cnt_total[BB*NE];        // pre-capacity top1 counts
__device__ float g_part_loss[BB*NE];
__device__ float g_ein [(size_t)NSLOT*DIMM];   // 64 MB
__device__ float g_hid [(size_t)NSLOT*HID];    // 256 MB
__device__ float g_eout[(size_t)NSLOT*DIMM];   // 64 MB

// ------------------------------- init ---------------------------------------
__global__ void init_kernel() {
    int i = blockIdx.x * blockDim.x + threadIdx.x;
    if (i < NSLOT) g_slot_token[i] = -1;
}

// ------------------------------ gating --------------------------------------
// fp32 pipeline with FTZ-emulating exp/divide (XLA GPU compiles f32 with ftz;
// XLA CPU's Eigen pexp zeroes in the same range): probabilities that underflow
// the NORMAL range become EXACTLY 0. Consequence faithfully reproduced: for
// tokens whose non-top-1 gates are all 0, argmax(gates_wo1) = index 0, so the
// token joins EXPERT 0's top-2 capacity chain with gate_2 = 0 (shifting later
// expert-0 positions). gate_2 is read from the masked array (gates_wo1), so
// the degenerate i2==i1 case yields 0, not p[i1].
__global__ void gating_kernel(const float* __restrict__ x,
                              const float* __restrict__ wg) {
    int e  = threadIdx.x & 15;          // expert
    int tt = threadIdx.x >> 4;          // token within block
    int tok = blockIdx.x * 16 + tt;
    const float* xr = x + (size_t)tok * DIMM;

    float acc = 0.f;
    #pragma unroll 8
    for (int d = 0; d < DIMM; d++)
        acc = fmaf(xr[d], wg[d * NE + e], acc);   // serial ascending-d fp32

    __shared__ float lg[16][17];
    lg[tt][e] = acc;
    __syncthreads();

    if (threadIdx.x < 16) {
        int t0 = threadIdx.x;
        int gtok = blockIdx.x * 16 + t0;
        float l[NE], p[NE];
        #pragma unroll
        for (int i = 0; i < NE; i++) l[i] = lg[t0][i];

        float m = l[0];
        #pragma unroll
        for (int i = 1; i < NE; i++) m = fmaxf(m, l[i]);
        float s = 0.f;
        #pragma unroll
        for (int i = 0; i < NE; i++) {
            float t = l[i] - m;
            float pe = (t < EXP_FTZ_CUT) ? 0.f : expf(t);   // FTZ exp
            p[i] = pe; s = s + pe;
        }
        #pragma unroll
        for (int i = 0; i < NE; i++) {
            float q = p[i] / s;
            if (q < FLT_MIN_NORM) q = 0.f;                  // FTZ divide
            p[i] = q;
        }

        // argmax raw_gates, first-index tie-break
        int i1 = 0; float p1 = p[0];
        #pragma unroll
        for (int i = 1; i < NE; i++) if (p[i] > p1) { p1 = p[i]; i1 = i; }
        // gates_wo1 = p * (1 - one_hot(i1)); argmax, first-index tie-break.
        // NOTE: if all gw are 0 this yields i2 = 0 (possibly == i1), exactly
        // like jnp.argmax on an all-zero row.
        float gw[NE];
        #pragma unroll
        for (int i = 0; i < NE; i++) gw[i] = (i == i1) ? 0.f : p[i];
        int i2 = 0; float p2v = gw[0];
        #pragma unroll
        for (int i = 1; i < NE; i++) if (gw[i] > p2v) { p2v = gw[i]; i2 = i; }

        float den = p1 + p2v + 1e-9f;    // gate_2 taken from gates_wo1 (p2v)
        g_e1[gtok] = i1; g_e2[gtok] = i2;
        g_g1[gtok] = p1 / den; g_g2[gtok] = p2v / den;
        #pragma unroll
        for (int i = 0; i < NE; i++) g_probs[gtok * NE + i] = p[i];
    }
}

// --------------------------- capacity / assign -------------------------------
// one block per (b, e): exclusive scan over the 2048 tokens (deterministic)
__global__ void assign_kernel() {
    const int T = 256, TPT = NN / T; // 8 tokens per thread
    int b = blockIdx.x / NE, e = blockIdx.x % NE;
    int t = threadIdx.x;
    __shared__ int s[T];

    // ---- pass 1: top-1 mask ----
    int flag[TPT], loc[TPT]; int c = 0;
    #pragma unroll
    for (int i = 0; i < TPT; i++) {
        int n = t * TPT + i;
        int f = (g_e1[b * NN + n] == e);
        flag[i] = f; loc[i] = c; c += f;
    }
    s[t] = c; __syncthreads();
    for (int off = 1; off < T; off <<= 1) {
        int v = (t >= off) ? s[t - off] : 0;
        __syncthreads(); s[t] += v; __syncthreads();
    }
    int total = s[T - 1];
    int excl  = s[t] - c;
    #pragma unroll
    for (int i = 0; i < TPT; i++) {
        if (flag[i]) {
            int n = t * TPT + i, gi = b * NN + n;
            int pos = excl + loc[i];
            if (pos < CAP) {
                int slot = (e * BB + b) * CAP + pos;
                g_slot1[gi] = slot;
                g_slot_token[slot] = gi;
            } else g_slot1[gi] = -1;
        }
    }
    if (t == 0) g_cnt_total[b * NE + e] = total;
    int kept1 = total < CAP ? total : CAP;
    __syncthreads();

    // ---- pass 2: top-2 mask, offset by kept top-1 count ----
    c = 0;
    #pragma unroll
    for (int i = 0; i < TPT; i++) {
        int n = t * TPT + i;
        int f = (g_e2[b * NN + n] == e);
        flag[i] = f; loc[i] = c; c += f;
    }
    s[t] = c; __syncthreads();
    for (int off = 1; off < T; off <<= 1) {
        int v = (t >= off) ? s[t - off] : 0;
        __syncthreads(); s[t] += v; __syncthreads();
    }
    excl = s[t] - c;
    #pragma unroll
    for (int i = 0; i < TPT; i++) {
        if (flag[i]) {
            int n = t * TPT + i, gi = b * NN + n;
            int pos = excl + loc[i] + kept1;
            if (pos < CAP) {
                int slot = (e * BB + b) * CAP + pos;
                g_slot2[gi] = slot;
                g_slot_token[slot] = gi;
            } else g_slot2[gi] = -1;
        }
    }
}

// ------------------------------- gather --------------------------------------
__global__ void gather_kernel(const float* __restrict__ x) {
    int row = blockIdx.x;
    int tok = g_slot_token[row];
    float4* dst = (float4*)(g_ein + (size_t)row * DIMM);
    if (tok >= 0) {
        const float4* src = (const float4*)(x + (size_t)tok * DIMM);
        dst[threadIdx.x] = src[threadIdx.x];
    } else {
        dst[threadIdx.x] = make_float4(0.f, 0.f, 0.f, 0.f);
    }
}

// ------------------------------- FFN GEMMs -----------------------------------
// C[r, n] = sum_k A[r, k] * W[expert(r)][k][n] (+ bias, optional GELU)
// strict fp32. 128x128x16 tile, 256 threads, 8x8 microtile.
template<int KDIM, int NDIM, bool FIRST>
__global__ __launch_bounds__(256) void ffn_gemm(const float* __restrict__ W,
                                                const float* __restrict__ bias) {
    const float* __restrict__ A = FIRST ? g_ein : g_hid;
    float* __restrict__ C       = FIRST ? g_hid : g_eout;

    const int BM = 128, BN = 128, BK = 16;
    int bx = blockIdx.x;            // NDIM / 128
    int by = blockIdx.y;            // NSLOT / 128
    int rowBase = by * BM;
    int e = rowBase / (BB * CAP);   // 1024 rows per expert
    const float* Wp = W + (size_t)e * KDIM * NDIM;

    __shared__ float As[BK][BM];
    __shared__ float Bs[BK][BN];

    int t  = threadIdx.x;
    int tx = t & 15;                // 0..15 (col group)
    int ty = t >> 4;                // 0..15 (row group)

    float acc[8][8];
    #pragma unroll
    for (int i = 0; i < 8; i++)
        #pragma unroll
        for (int j = 0; j < 8; j++) acc[i][j] = 0.f;

    for (int k0 = 0; k0 < KDIM; k0 += BK) {
        #pragma unroll
        for (int i = 0; i < 2; i++) {
            int idx = t + i * 256;          // 0..511 float4s
            int r   = idx >> 2;
            int c4  = (idx & 3) * 4;
            float4 v = *(const float4*)(A + (size_t)(rowBase + r) * KDIM + k0 + c4);
            As[c4 + 0][r] = v.x; As[c4 + 1][r] = v.y;
            As[c4 + 2][r] = v.z; As[c4 + 3][r] = v.w;
        }
        #pragma unroll
        for (int i = 0; i < 2; i++) {
            int idx = t + i * 256;
            int r   = idx >> 5;
            int c4  = (idx & 31) * 4;
            *(float4*)(&Bs[r][c4]) =
                *(const float4*)(Wp + (size_t)(k0 + r) * NDIM + bx * BN + c4);
        }
        __syncthreads();

        #pragma unroll
        for (int kk = 0; kk < BK; kk++) {
            float a[8], b[8];
            *(float4*)(a)     = *(const float4*)(&As[kk][ty * 8]);
            *(float4*)(a + 4) = *(const float4*)(&As[kk][ty * 8 + 4]);
            *(float4*)(b)     = *(const float4*)(&Bs[kk][tx * 8]);
            *(float4*)(b + 4) = *(const float4*)(&Bs[kk][tx * 8 + 4]);
            #pragma unroll
            for (int i = 0; i < 8; i++)
                #pragma unroll
                for (int j = 0; j < 8; j++)
                    acc[i][j] += a[i] * b[j];
        }
        __syncthreads();
    }

    #pragma unroll
    for (int i = 0; i < 8; i++) {
        size_t r = (size_t)(rowBase + ty * 8 + i);
        #pragma unroll
        for (int j = 0; j < 8; j += 4) {
            int col = bx * BN + tx * 8 + j;
            float4 v;
            v.x = acc[i][j + 0] + bias[col + 0];
            v.y = acc[i][j + 1] + bias[col + 1];
            v.z = acc[i][j + 2] + bias[col + 2];
            v.w = acc[i][j + 3] + bias[col + 3];
            if (FIRST) { // exact GELU
                v.x = 0.5f * v.x * (1.f + erff(v.x * 0.70710678118654752f));
                v.y = 0.5f * v.y * (1.f + erff(v.y * 0.70710678118654752f));
                v.z = 0.5f * v.z * (1.f + erff(v.z * 0.70710678118654752f));
                v.w = 0.5f * v.w * (1.f + erff(v.w * 0.70710678118654752f));
            }
            *(float4*)(&C[r * NDIM + col]) = v;
        }
    }
}

// ------------------------------- combine -------------------------------------
__global__ void combine_kernel(float* __restrict__ out) {
    int tok = blockIdx.x;
    int t   = threadIdx.x;          // 256 threads x float4 = 1024 floats
    int s1 = g_slot1[tok], s2 = g_slot2[tok];
    float g1 = (s1 >= 0) ? g_g1[tok] : 0.f;
    float g2 = (s2 >= 0) ? g_g2[tok] : 0.f;
    float4 v = make_float4(0.f, 0.f, 0.f, 0.f);
    if (s1 >= 0) {
        float4 a = ((const float4*)(g_eout + (size_t)s1 * DIMM))[t];
        v.x += g1 * a.x; v.y += g1 * a.y; v.z += g1 * a.z; v.w += g1 * a.w;
    }
    if (s2 >= 0) {
        float4 a = ((const float4*)(g_eout + (size_t)s2 * DIMM))[t];
        v.x += g2 * a.x; v.y += g2 * a.y; v.z += g2 * a.z; v.w += g2 * a.w;
    }
    ((float4*)(out + (size_t)tok * DIMM))[t] = v;
}

// -------------------------------- loss ---------------------------------------
__global__ void loss_part_kernel() {
    int be = blockIdx.x;            // 64 blocks
    int b = be / NE, e = be % NE;
    __shared__ float s[256];
    float acc = 0.f;
    for (int n = threadIdx.x; n < NN; n += 256)
        acc += g_probs[(size_t)(b * NN + n) * NE + e];
    s[threadIdx.x] = acc; __syncthreads();
    for (int off = 128; off; off >>= 1) {
        if (threadIdx.x < off) s[threadIdx.x] += s[threadIdx.x + off];
        __syncthreads();
    }
    if (threadIdx.x == 0)
        g_part_loss[be] = (s[0] / (float)NN) *
                          ((float)g_cnt_total[be] / (float)NN);
}

__global__ void loss_final_kernel(float* __restrict__ out) {
    __shared__ float s[64];
    int t = threadIdx.x;
    s[t] = g_part_loss[t]; __syncthreads();
    for (int off = 32; off; off >>= 1) {
        if (t < off) s[t] += s[t + off];
        __syncthreads();
    }
    // (1/64)*sum * NE^2 * LOSS_COEF == sum * 0.04
    if (t == 0) out[(size_t)NTOK * DIMM] = s[0] * 0.04f;
}

// ------------------------------- launch --------------------------------------
extern "C" void kernel_launch(void* const* d_in, const int* in_sizes, int n_in,
                              void* d_out, int out_size) {
    const float* x  = (const float*)d_in[0];
    const float* wg = (const float*)d_in[1];
    const float* w1 = (const float*)d_in[2];
    const float* w2 = (const float*)d_in[3];
    const float* b1 = (const float*)d_in[4];
    const float* b2 = (const float*)d_in[5];
    float* out = (float*)d_out;

    init_kernel<<<(NSLOT + 255) / 256, 256>>>();
    gating_kernel<<<NTOK / 16, 256>>>(x, wg);
    assign_kernel<<<BB * NE, 256>>>();
    gather_kernel<<<NSLOT, 256>>>(x);
    ffn_gemm<DIMM, HID,  true ><<<dim3(HID  / 128, NSLOT / 128), 256>>>(w1, b1);
    ffn_gemm<HID,  DIMM, false><<<dim3(DIMM / 128, NSLOT / 128), 256>>>(w2, b2);
    combine_kernel<<<NTOK, 256>>>(out);
    loss_part_kernel<<<BB * NE, 256>>>();
    if (out_size > NTOK * DIMM)
        loss_final_kernel<<<1, 64>>>(out);
}

// round 9
// speedup vs baseline: 3.5139x; 3.5139x over previous
#include <cuda_runtime.h>
#include <cuda_fp16.h>
#include <mma.h>
#include <math.h>
#include <stdint.h>

#define BB   4
#define NN   2048
#define DIMM 1024
#define HID  4096
#define NE   16
#define CAP  256
#define NTOK (BB*NN)          // 8192 tokens
#define NSLOT (NE*BB*CAP)     // 16384 expert slot rows
#define FLT_MIN_NORM 1.17549435e-38f
#define EXP_FTZ_CUT  (-87.336544f)

using namespace nvcuda;

// ------------------------- scratch (device globals) -------------------------
__device__ float g_probs[NTOK*NE];
__device__ int   g_e1[NTOK], g_e2[NTOK];
__device__ float g_g1[NTOK], g_g2[NTOK];
__device__ int   g_slot1[NTOK], g_slot2[NTOK];
__device__ int   g_slot_token[NSLOT];
__device__ int   g_cnt_total[BB*NE];
__device__ float g_part_loss[BB*NE];
__device__ float g_ein [(size_t)NSLOT*DIMM];   // 64 MB
__device__ float g_hid [(size_t)NSLOT*HID];    // 256 MB
__device__ float g_eout[(size_t)NSLOT*DIMM];   // 64 MB

// ------------------------------- init ---------------------------------------
__global__ void init_kernel() {
    int i = blockIdx.x * blockDim.x + threadIdx.x;
    if (i < NSLOT) g_slot_token[i] = -1;
}

// ------------------------------ gating (GOLDEN — do not touch) ---------------
__global__ void gating_kernel(const float* __restrict__ x,
                              const float* __restrict__ wg) {
    int e  = threadIdx.x & 15;
    int tt = threadIdx.x >> 4;
    int tok = blockIdx.x * 16 + tt;
    const float* xr = x + (size_t)tok * DIMM;

    float acc = 0.f;
    #pragma unroll 8
    for (int d = 0; d < DIMM; d++)
        acc = fmaf(xr[d], wg[d * NE + e], acc);

    __shared__ float lg[16][17];
    lg[tt][e] = acc;
    __syncthreads();

    if (threadIdx.x < 16) {
        int t0 = threadIdx.x;
        int gtok = blockIdx.x * 16 + t0;
        float l[NE], p[NE];
        #pragma unroll
        for (int i = 0; i < NE; i++) l[i] = lg[t0][i];

        float m = l[0];
        #pragma unroll
        for (int i = 1; i < NE; i++) m = fmaxf(m, l[i]);
        float s = 0.f;
        #pragma unroll
        for (int i = 0; i < NE; i++) {
            float t = l[i] - m;
            float pe = (t < EXP_FTZ_CUT) ? 0.f : expf(t);   // FTZ exp
            p[i] = pe; s = s + pe;
        }
        #pragma unroll
        for (int i = 0; i < NE; i++) {
            float q = p[i] / s;
            if (q < FLT_MIN_NORM) q = 0.f;                  // FTZ divide
            p[i] = q;
        }

        int i1 = 0; float p1 = p[0];
        #pragma unroll
        for (int i = 1; i < NE; i++) if (p[i] > p1) { p1 = p[i]; i1 = i; }
        float gw[NE];
        #pragma unroll
        for (int i = 0; i < NE; i++) gw[i] = (i == i1) ? 0.f : p[i];
        int i2 = 0; float p2v = gw[0];
        #pragma unroll
        for (int i = 1; i < NE; i++) if (gw[i] > p2v) { p2v = gw[i]; i2 = i; }

        float den = p1 + p2v + 1e-9f;
        g_e1[gtok] = i1; g_e2[gtok] = i2;
        g_g1[gtok] = p1 / den; g_g2[gtok] = p2v / den;
        #pragma unroll
        for (int i = 0; i < NE; i++) g_probs[gtok * NE + i] = p[i];
    }
}

// --------------------------- capacity / assign -------------------------------
__global__ void assign_kernel() {
    const int T = 256, TPT = NN / T;
    int b = blockIdx.x / NE, e = blockIdx.x % NE;
    int t = threadIdx.x;
    __shared__ int s[T];

    int flag[TPT], loc[TPT]; int c = 0;
    #pragma unroll
    for (int i = 0; i < TPT; i++) {
        int n = t * TPT + i;
        int f = (g_e1[b * NN + n] == e);
        flag[i] = f; loc[i] = c; c += f;
    }
    s[t] = c; __syncthreads();
    for (int off = 1; off < T; off <<= 1) {
        int v = (t >= off) ? s[t - off] : 0;
        __syncthreads(); s[t] += v; __syncthreads();
    }
    int total = s[T - 1];
    int excl  = s[t] - c;
    #pragma unroll
    for (int i = 0; i < TPT; i++) {
        if (flag[i]) {
            int n = t * TPT + i, gi = b * NN + n;
            int pos = excl + loc[i];
            if (pos < CAP) {
                int slot = (e * BB + b) * CAP + pos;
                g_slot1[gi] = slot;
                g_slot_token[slot] = gi;
            } else g_slot1[gi] = -1;
        }
    }
    if (t == 0) g_cnt_total[b * NE + e] = total;
    int kept1 = total < CAP ? total : CAP;
    __syncthreads();

    c = 0;
    #pragma unroll
    for (int i = 0; i < TPT; i++) {
        int n = t * TPT + i;
        int f = (g_e2[b * NN + n] == e);
        flag[i] = f; loc[i] = c; c += f;
    }
    s[t] = c; __syncthreads();
    for (int off = 1; off < T; off <<= 1) {
        int v = (t >= off) ? s[t - off] : 0;
        __syncthreads(); s[t] += v; __syncthreads();
    }
    excl = s[t] - c;
    #pragma unroll
    for (int i = 0; i < TPT; i++) {
        if (flag[i]) {
            int n = t * TPT + i, gi = b * NN + n;
            int pos = excl + loc[i] + kept1;
            if (pos < CAP) {
                int slot = (e * BB + b) * CAP + pos;
                g_slot2[gi] = slot;
                g_slot_token[slot] = gi;
            } else g_slot2[gi] = -1;
        }
    }
}

// ------------------------------- gather --------------------------------------
__global__ void gather_kernel(const float* __restrict__ x) {
    int row = blockIdx.x;
    int tok = g_slot_token[row];
    float4* dst = (float4*)(g_ein + (size_t)row * DIMM);
    if (tok >= 0) {
        const float4* src = (const float4*)(x + (size_t)tok * DIMM);
        dst[threadIdx.x] = src[threadIdx.x];
    } else {
        dst[threadIdx.x] = make_float4(0.f, 0.f, 0.f, 0.f);
    }
}

// ----------------------- WMMA fp16 GEMM (tensor pipe) ------------------------
// C[r,n] = sum_k A[r,k]*W[e][k][n] (+bias, GELU if FIRST).
// Block 128x128x32, 8 warps, warp tile 32x64 (2x4 m16n16k16 frags).
// fp32 global -> fp16 smem (round-to-nearest), fp32 accumulate.
__device__ __forceinline__ float gelu_exact(float v) {
    return 0.5f * v * (1.f + erff(v * 0.70710678118654752f));
}

template<int KDIM, int NDIM, bool FIRST>
__global__ void __launch_bounds__(256, 2) hgemm(const float* __restrict__ W,
                                                const float* __restrict__ bias) {
    const float* __restrict__ A = FIRST ? g_ein : g_hid;
    float* __restrict__ C       = FIRST ? g_hid : g_eout;

    constexpr int BM = 128, BN = 128, BK = 32;
    constexpr int NC = KDIM / BK;
    __shared__ __align__(16) half  As[2][BM][BK + 8];  // rows 80B (16B mult)
    __shared__ __align__(16) half  Bs[2][BK][BN + 8];  // rows 272B (16B mult)
    __shared__ __align__(16) float epi[8][16][20];     // ldm=20 (mult of 4!)

    const int bx = blockIdx.x, by = blockIdx.y;
    const int rowBase = by * BM, colBase = bx * BN;
    const int e = rowBase >> 10;            // 1024 rows per expert
    const float* __restrict__ Wp = W + (size_t)e * KDIM * NDIM;
    const int tid = threadIdx.x, wid = tid >> 5, lane = tid & 31;
    const int wm = (wid & 3) * 32, wn = (wid >> 2) * 64;

    // A copy mapping: row = tid>>1 (0..127), 16 cols starting at (tid&1)*16
    const int ar = tid >> 1, ac = (tid & 1) * 16;
    // B copy mapping: row = tid>>3 (0..31), 16 cols starting at (tid&7)*16
    const int br = tid >> 3, bc = (tid & 7) * 16;

    wmma::fragment<wmma::accumulator, 16, 16, 16, float> acc[2][4];
    #pragma unroll
    for (int i = 0; i < 2; i++)
        #pragma unroll
        for (int j = 0; j < 4; j++) wmma::fill_fragment(acc[i][j], 0.f);

    // ---- preload chunk 0 ----
    {
        const float* sa = A + (size_t)(rowBase + ar) * KDIM + ac;
        #pragma unroll
        for (int j = 0; j < 16; j += 4) {
            float4 v = *(const float4*)(sa + j);
            As[0][ar][ac + j + 0] = __float2half_rn(v.x);
            As[0][ar][ac + j + 1] = __float2half_rn(v.y);
            As[0][ar][ac + j + 2] = __float2half_rn(v.z);
            As[0][ar][ac + j + 3] = __float2half_rn(v.w);
        }
        const float* sbp = Wp + (size_t)br * NDIM + colBase + bc;
        #pragma unroll
        for (int j = 0; j < 16; j += 4) {
            float4 v = *(const float4*)(sbp + j);
            Bs[0][br][bc + j + 0] = __float2half_rn(v.x);
            Bs[0][br][bc + j + 1] = __float2half_rn(v.y);
            Bs[0][br][bc + j + 2] = __float2half_rn(v.z);
            Bs[0][br][bc + j + 3] = __float2half_rn(v.w);
        }
    }
    __syncthreads();

    for (int c = 0; c < NC; c++) {
        const int cur = c & 1, nxt = cur ^ 1;
        float4 ra[4], rb[4];
        if (c + 1 < NC) {                       // issue next-chunk LDGs early
            const float* sa = A + (size_t)(rowBase + ar) * KDIM + (c + 1) * BK + ac;
            #pragma unroll
            for (int j = 0; j < 4; j++) ra[j] = *(const float4*)(sa + j * 4);
            const float* sbp = Wp + (size_t)((c + 1) * BK + br) * NDIM + colBase + bc;
            #pragma unroll
            for (int j = 0; j < 4; j++) rb[j] = *(const float4*)(sbp + j * 4);
        }

        // compute on current buffers (hides the LDG latency above)
        #pragma unroll
        for (int kk = 0; kk < 2; kk++) {
            wmma::fragment<wmma::matrix_a, 16, 16, 16, half, wmma::row_major> af[2];
            wmma::fragment<wmma::matrix_b, 16, 16, 16, half, wmma::row_major> bf[4];
            wmma::load_matrix_sync(af[0], &As[cur][wm     ][kk * 16], BK + 8);
            wmma::load_matrix_sync(af[1], &As[cur][wm + 16][kk * 16], BK + 8);
            #pragma unroll
            for (int j = 0; j < 4; j++)
                wmma::load_matrix_sync(bf[j], &Bs[cur][kk * 16][wn + j * 16], BN + 8);
            #pragma unroll
            for (int i = 0; i < 2; i++)
                #pragma unroll
                for (int j = 0; j < 4; j++)
                    wmma::mma_sync(acc[i][j], af[i], bf[j], acc[i][j]);
        }

        if (c + 1 < NC) {                       // convert + store staged data
            #pragma unroll
            for (int j = 0; j < 4; j++) {
                As[nxt][ar][ac + j * 4 + 0] = __float2half_rn(ra[j].x);
                As[nxt][ar][ac + j * 4 + 1] = __float2half_rn(ra[j].y);
                As[nxt][ar][ac + j * 4 + 2] = __float2half_rn(ra[j].z);
                As[nxt][ar][ac + j * 4 + 3] = __float2half_rn(ra[j].w);
            }
            #pragma unroll
            for (int j = 0; j < 4; j++) {
                Bs[nxt][br][bc + j * 4 + 0] = __float2half_rn(rb[j].x);
                Bs[nxt][br][bc + j * 4 + 1] = __float2half_rn(rb[j].y);
                Bs[nxt][br][bc + j * 4 + 2] = __float2half_rn(rb[j].z);
                Bs[nxt][br][bc + j * 4 + 3] = __float2half_rn(rb[j].w);
            }
        }
        __syncthreads();
    }

    // ---- epilogue: per-warp smem staging, bias + GELU, coalesced store ----
    #pragma unroll
    for (int i = 0; i < 2; i++) {
        #pragma unroll
        for (int j = 0; j < 4; j++) {
            wmma::store_matrix_sync(&epi[wid][0][0], acc[i][j], 20,
                                    wmma::mem_row_major);
            __syncwarp();
            int r0 = rowBase + wm + i * 16;
            int c0 = colBase + wn + j * 16;
            int colOff = lane & 15;
            float bv = bias[c0 + colOff];
            #pragma unroll
            for (int q = 0; q < 8; q++) {
                int idx = q * 32 + lane;        // row = idx>>4, col = idx&15
                int row = idx >> 4;
                float v = epi[wid][row][colOff] + bv;
                if (FIRST) v = gelu_exact(v);
                C[(size_t)(r0 + row) * NDIM + c0 + colOff] = v;
            }
            __syncwarp();
        }
    }
}

// ------------------------------- combine -------------------------------------
__global__ void combine_kernel(float* __restrict__ out) {
    int tok = blockIdx.x;
    int t   = threadIdx.x;
    int s1 = g_slot1[tok], s2 = g_slot2[tok];
    float g1 = (s1 >= 0) ? g_g1[tok] : 0.f;
    float g2 = (s2 >= 0) ? g_g2[tok] : 0.f;
    float4 v = make_float4(0.f, 0.f, 0.f, 0.f);
    if (s1 >= 0) {
        float4 a = ((const float4*)(g_eout + (size_t)s1 * DIMM))[t];
        v.x += g1 * a.x; v.y += g1 * a.y; v.z += g1 * a.z; v.w += g1 * a.w;
    }
    if (s2 >= 0) {
        float4 a = ((const float4*)(g_eout + (size_t)s2 * DIMM))[t];
        v.x += g2 * a.x; v.y += g2 * a.y; v.z += g2 * a.z; v.w += g2 * a.w;
    }
    ((float4*)(out + (size_t)tok * DIMM))[t] = v;
}

// -------------------------------- loss ---------------------------------------
__global__ void loss_part_kernel() {
    int be = blockIdx.x;
    int b = be / NE, e = be % NE;
    __shared__ float s[256];
    float acc = 0.f;
    for (int n = threadIdx.x; n < NN; n += 256)
        acc += g_probs[(size_t)(b * NN + n) * NE + e];
    s[threadIdx.x] = acc; __syncthreads();
    for (int off = 128; off; off >>= 1) {
        if (threadIdx.x < off) s[threadIdx.x] += s[threadIdx.x + off];
        __syncthreads();
    }
    if (threadIdx.x == 0)
        g_part_loss[be] = (s[0] / (float)NN) *
                          ((float)g_cnt_total[be] / (float)NN);
}

__global__ void loss_final_kernel(float* __restrict__ out) {
    __shared__ float s[64];
    int t = threadIdx.x;
    s[t] = g_part_loss[t]; __syncthreads();
    for (int off = 32; off; off >>= 1) {
        if (t < off) s[t] += s[t + off];
        __syncthreads();
    }
    if (t == 0) out[(size_t)NTOK * DIMM] = s[0] * 0.04f;
}

// ------------------------------- launch --------------------------------------
extern "C" void kernel_launch(void* const* d_in, const int* in_sizes, int n_in,
                              void* d_out, int out_size) {
    const float* x  = (const float*)d_in[0];
    const float* wg = (const float*)d_in[1];
    const float* w1 = (const float*)d_in[2];
    const float* w2 = (const float*)d_in[3];
    const float* b1 = (const float*)d_in[4];
    const float* b2 = (const float*)d_in[5];
    float* out = (float*)d_out;

    init_kernel<<<(NSLOT + 255) / 256, 256>>>();
    gating_kernel<<<NTOK / 16, 256>>>(x, wg);
    assign_kernel<<<BB * NE, 256>>>();
    gather_kernel<<<NSLOT, 256>>>(x);
    hgemm<DIMM, HID,  true ><<<dim3(HID  / 128, NSLOT / 128), 256>>>(w1, b1);
    hgemm<HID,  DIMM, false><<<dim3(DIMM / 128, NSLOT / 128), 256>>>(w2, b2);
    combine_kernel<<<NTOK, 256>>>(out);
    loss_part_kernel<<<BB * NE, 256>>>();
    if (out_size > NTOK * DIMM)
        loss_final_kernel<<<1, 64>>>(out);
}

// round 10
// speedup vs baseline: 5.9705x; 1.6991x over previous
#include <cuda_runtime.h>
#include <cuda_fp16.h>
#include <mma.h>
#include <math.h>
#include <stdint.h>

#define BB   4
#define NN   2048
#define DIMM 1024
#define HID  4096
#define NE   16
#define CAP  256
#define NTOK (BB*NN)          // 8192 tokens
#define NSLOT (NE*BB*CAP)     // 16384 expert slot rows
#define FLT_MIN_NORM 1.17549435e-38f
#define EXP_FTZ_CUT  (-87.336544f)

using namespace nvcuda;

// ------------------------- scratch (device globals) -------------------------
__device__ float  g_probs[NTOK*NE];
__device__ int    g_e1[NTOK], g_e2[NTOK];
__device__ float  g_g1[NTOK], g_g2[NTOK];
__device__ int    g_slot1[NTOK], g_slot2[NTOK];
__device__ int    g_slot_token[NSLOT];
__device__ int    g_cnt_total[BB*NE];
__device__ float  g_part_loss[BB*NE];
__device__ __half g_einh[(size_t)NSLOT*DIMM];        // 32 MB
__device__ __half g_hidh[(size_t)NSLOT*HID];         // 128 MB
__device__ __half g_w1h [(size_t)NE*DIMM*HID];       // 128 MB
__device__ __half g_w2h [(size_t)NE*HID*DIMM];       // 128 MB
__device__ float  g_eout[(size_t)NSLOT*DIMM];        // 64 MB

// ------------------------- async-copy helpers --------------------------------
__device__ __forceinline__ uint32_t s2u(const void* p) {
    uint32_t a;
    asm("{ .reg .u64 t; cvta.to.shared.u64 t, %1; cvt.u32.u64 %0, t; }"
        : "=r"(a) : "l"(p));
    return a;
}
#define CP16(dst, src) \
    asm volatile("cp.async.cg.shared.global [%0], [%1], 16;" \
                 :: "r"(dst), "l"(src) : "memory")
#define CP_COMMIT() asm volatile("cp.async.commit_group;" ::: "memory")
#define CP_WAIT2()  asm volatile("cp.async.wait_group 2;" ::: "memory")

// ------------------------------- init ---------------------------------------
__global__ void init_kernel() {
    int i = blockIdx.x * blockDim.x + threadIdx.x;
    if (i < NSLOT) g_slot_token[i] = -1;
}

// -------------------------- weight fp32 -> fp16 ------------------------------
__global__ void wconv_kernel(const float4* __restrict__ src, int which, int n4) {
    uint2* __restrict__ dst = which ? (uint2*)g_w2h : (uint2*)g_w1h;
    int i = blockIdx.x * blockDim.x + threadIdx.x;
    int stride = gridDim.x * blockDim.x;
    for (; i < n4; i += stride) {
        float4 v = src[i];
        __half2 h0 = __floats2half2_rn(v.x, v.y);
        __half2 h1 = __floats2half2_rn(v.z, v.w);
        uint2 o; o.x = *(uint32_t*)&h0; o.y = *(uint32_t*)&h1;
        dst[i] = o;
    }
}

// ------------------------------ gating (GOLDEN — do not touch) ---------------
__global__ void gating_kernel(const float* __restrict__ x,
                              const float* __restrict__ wg) {
    int e  = threadIdx.x & 15;
    int tt = threadIdx.x >> 4;
    int tok = blockIdx.x * 16 + tt;
    const float* xr = x + (size_t)tok * DIMM;

    float acc = 0.f;
    #pragma unroll 8
    for (int d = 0; d < DIMM; d++)
        acc = fmaf(xr[d], wg[d * NE + e], acc);

    __shared__ float lg[16][17];
    lg[tt][e] = acc;
    __syncthreads();

    if (threadIdx.x < 16) {
        int t0 = threadIdx.x;
        int gtok = blockIdx.x * 16 + t0;
        float l[NE], p[NE];
        #pragma unroll
        for (int i = 0; i < NE; i++) l[i] = lg[t0][i];

        float m = l[0];
        #pragma unroll
        for (int i = 1; i < NE; i++) m = fmaxf(m, l[i]);
        float s = 0.f;
        #pragma unroll
        for (int i = 0; i < NE; i++) {
            float t = l[i] - m;
            float pe = (t < EXP_FTZ_CUT) ? 0.f : expf(t);   // FTZ exp
            p[i] = pe; s = s + pe;
        }
        #pragma unroll
        for (int i = 0; i < NE; i++) {
            float q = p[i] / s;
            if (q < FLT_MIN_NORM) q = 0.f;                  // FTZ divide
            p[i] = q;
        }

        int i1 = 0; float p1 = p[0];
        #pragma unroll
        for (int i = 1; i < NE; i++) if (p[i] > p1) { p1 = p[i]; i1 = i; }
        float gw[NE];
        #pragma unroll
        for (int i = 0; i < NE; i++) gw[i] = (i == i1) ? 0.f : p[i];
        int i2 = 0; float p2v = gw[0];
        #pragma unroll
        for (int i = 1; i < NE; i++) if (gw[i] > p2v) { p2v = gw[i]; i2 = i; }

        float den = p1 + p2v + 1e-9f;
        g_e1[gtok] = i1; g_e2[gtok] = i2;
        g_g1[gtok] = p1 / den; g_g2[gtok] = p2v / den;
        #pragma unroll
        for (int i = 0; i < NE; i++) g_probs[gtok * NE + i] = p[i];
    }
}

// --------------------------- capacity / assign -------------------------------
__global__ void assign_kernel() {
    const int T = 256, TPT = NN / T;
    int b = blockIdx.x / NE, e = blockIdx.x % NE;
    int t = threadIdx.x;
    __shared__ int s[T];

    int flag[TPT], loc[TPT]; int c = 0;
    #pragma unroll
    for (int i = 0; i < TPT; i++) {
        int n = t * TPT + i;
        int f = (g_e1[b * NN + n] == e);
        flag[i] = f; loc[i] = c; c += f;
    }
    s[t] = c; __syncthreads();
    for (int off = 1; off < T; off <<= 1) {
        int v = (t >= off) ? s[t - off] : 0;
        __syncthreads(); s[t] += v; __syncthreads();
    }
    int total = s[T - 1];
    int excl  = s[t] - c;
    #pragma unroll
    for (int i = 0; i < TPT; i++) {
        if (flag[i]) {
            int n = t * TPT + i, gi = b * NN + n;
            int pos = excl + loc[i];
            if (pos < CAP) {
                int slot = (e * BB + b) * CAP + pos;
                g_slot1[gi] = slot;
                g_slot_token[slot] = gi;
            } else g_slot1[gi] = -1;
        }
    }
    if (t == 0) g_cnt_total[b * NE + e] = total;
    int kept1 = total < CAP ? total : CAP;
    __syncthreads();

    c = 0;
    #pragma unroll
    for (int i = 0; i < TPT; i++) {
        int n = t * TPT + i;
        int f = (g_e2[b * NN + n] == e);
        flag[i] = f; loc[i] = c; c += f;
    }
    s[t] = c; __syncthreads();
    for (int off = 1; off < T; off <<= 1) {
        int v = (t >= off) ? s[t - off] : 0;
        __syncthreads(); s[t] += v; __syncthreads();
    }
    excl = s[t] - c;
    #pragma unroll
    for (int i = 0; i < TPT; i++) {
        if (flag[i]) {
            int n = t * TPT + i, gi = b * NN + n;
            int pos = excl + loc[i] + kept1;
            if (pos < CAP) {
                int slot = (e * BB + b) * CAP + pos;
                g_slot2[gi] = slot;
                g_slot_token[slot] = gi;
            } else g_slot2[gi] = -1;
        }
    }
}

// ------------------------------- gather (fp32 -> fp16) -----------------------
__global__ void gather_kernel(const float* __restrict__ x) {
    int row = blockIdx.x;
    int tok = g_slot_token[row];
    uint2* dst = (uint2*)(g_einh + (size_t)row * DIMM);
    int t = threadIdx.x;                 // 256 threads x 4 halves
    if (tok >= 0) {
        float4 v = ((const float4*)(x + (size_t)tok * DIMM))[t];
        __half2 h0 = __floats2half2_rn(v.x, v.y);
        __half2 h1 = __floats2half2_rn(v.z, v.w);
        uint2 o; o.x = *(uint32_t*)&h0; o.y = *(uint32_t*)&h1;
        dst[t] = o;
    } else {
        dst[t] = make_uint2(0u, 0u);
    }
}

// ----------------- WMMA fp16 GEMM, cp.async 4-stage pipeline -----------------
// C[r,n] = sum_k A[r,k]*W[e][k][n] (+bias, GELU if FIRST).
// 128x128x32 tile, 8 warps x (32x64), fp16 operands in gmem, fp32 accum.
__device__ __forceinline__ float gelu_exact(float v) {
    return 0.5f * v * (1.f + erff(v * 0.70710678118654752f));
}

template<int KDIM, int NDIM, bool FIRST>
__global__ void __launch_bounds__(256, 2) hgemm(const float* __restrict__ bias) {
    const __half* __restrict__ A  = FIRST ? g_einh : g_hidh;
    const __half* __restrict__ Wh = FIRST ? g_w1h  : g_w2h;

    constexpr int BM = 128, BN = 128, BK = 32;
    constexpr int NC = KDIM / BK;
    constexpr int ALD = 40;                       // halves per padded A row
    constexpr int BLD = 136;                      // halves per padded B row
    constexpr int ABYTES = BM * ALD * 2;          // 10240
    constexpr int STAGE  = ABYTES + BK * BLD * 2; // 18944

    extern __shared__ __align__(16) char dsm[];   // 4*STAGE = 75776 B

    const int tid = threadIdx.x, wid = tid >> 5, lane = tid & 31;
    const int bx = blockIdx.x, by = blockIdx.y;
    const int rowBase = by * BM, colBase = bx * BN;
    const int e = rowBase >> 10;
    const __half* __restrict__ Wp = Wh + (size_t)e * KDIM * NDIM;
    const __half* __restrict__ Ap = A + (size_t)rowBase * KDIM;
    const uint32_t sbase = s2u(dsm);
    const int wm = (wid & 3) * 32, wn = (wid >> 2) * 64;

    wmma::fragment<wmma::accumulator, 16, 16, 16, float> acc[2][4];
    #pragma unroll
    for (int i = 0; i < 2; i++)
        #pragma unroll
        for (int j = 0; j < 4; j++) wmma::fill_fragment(acc[i][j], 0.f);

    auto issue = [&](int s, int c) {
        uint32_t ab = sbase + s * STAGE;
        #pragma unroll
        for (int i = 0; i < 2; i++) {
            int ch = tid + i * 256;               // 512 chunks: 128 rows x 64B
            int r = ch >> 2, q = ch & 3;
            CP16(ab + r * 80 + q * 16, Ap + (size_t)r * KDIM + c * BK + q * 8);
        }
        uint32_t bb = sbase + s * STAGE + ABYTES;
        #pragma unroll
        for (int i = 0; i < 2; i++) {
            int ch = tid + i * 256;               // 512 chunks: 32 rows x 256B
            int r = ch >> 4, q = ch & 15;
            CP16(bb + r * 272 + q * 16,
                 Wp + (size_t)(c * BK + r) * NDIM + colBase + q * 8);
        }
    };

    #pragma unroll
    for (int s = 0; s < 3; s++) { issue(s, s); CP_COMMIT(); }

    for (int c = 0; c < NC; c++) {
        CP_WAIT2();
        __syncthreads();
        if (c + 3 < NC) issue((c + 3) & 3, c + 3);
        CP_COMMIT();                              // empty group at tail keeps count

        const __half* As_ = (const __half*)(dsm + (c & 3) * STAGE);
        const __half* Bs_ = (const __half*)(dsm + (c & 3) * STAGE + ABYTES);
        #pragma unroll
        for (int kk = 0; kk < 2; kk++) {
            wmma::fragment<wmma::matrix_a, 16, 16, 16, half, wmma::row_major> af[2];
            wmma::fragment<wmma::matrix_b, 16, 16, 16, half, wmma::row_major> bf[4];
            wmma::load_matrix_sync(af[0], As_ + (wm     ) * ALD + kk * 16, ALD);
            wmma::load_matrix_sync(af[1], As_ + (wm + 16) * ALD + kk * 16, ALD);
            #pragma unroll
            for (int j = 0; j < 4; j++)
                wmma::load_matrix_sync(bf[j], Bs_ + (kk * 16) * BLD + wn + j * 16, BLD);
            #pragma unroll
            for (int i = 0; i < 2; i++)
                #pragma unroll
                for (int j = 0; j < 4; j++)
                    wmma::mma_sync(acc[i][j], af[i], bf[j], acc[i][j]);
        }
        __syncthreads();
    }

    // ---- epilogue: restage 16x64 per warp in smem, vectorized stores ----
    float* epi = (float*)dsm + wid * 16 * 68;     // 16 rows x ldm 68
    #pragma unroll
    for (int i = 0; i < 2; i++) {
        #pragma unroll
        for (int j = 0; j < 4; j++)
            wmma::store_matrix_sync(epi + j * 16, acc[i][j], 68, wmma::mem_row_major);
        __syncwarp();
        int r0 = rowBase + wm + i * 16;
        int c0 = colBase + wn;
        if (FIRST) {
            __half* C = g_hidh;
            #pragma unroll
            for (int q = 0; q < 4; q++) {
                int sid = q * 32 + lane;
                int row = sid >> 3, c8 = (sid & 7) * 8;
                float4 b0 = *(const float4*)(&bias[c0 + c8]);
                float4 b1 = *(const float4*)(&bias[c0 + c8 + 4]);
                const float* er = epi + row * 68 + c8;
                float v0 = gelu_exact(er[0] + b0.x), v1 = gelu_exact(er[1] + b0.y);
                float v2 = gelu_exact(er[2] + b0.z), v3 = gelu_exact(er[3] + b0.w);
                float v4 = gelu_exact(er[4] + b1.x), v5 = gelu_exact(er[5] + b1.y);
                float v6 = gelu_exact(er[6] + b1.z), v7 = gelu_exact(er[7] + b1.w);
                __half2 h0 = __floats2half2_rn(v0, v1), h1 = __floats2half2_rn(v2, v3);
                __half2 h2 = __floats2half2_rn(v4, v5), h3 = __floats2half2_rn(v6, v7);
                uint4 o; o.x = *(uint32_t*)&h0; o.y = *(uint32_t*)&h1;
                o.z = *(uint32_t*)&h2; o.w = *(uint32_t*)&h3;
                *(uint4*)(&C[(size_t)(r0 + row) * NDIM + c0 + c8]) = o;
            }
        } else {
            float* C = g_eout;
            #pragma unroll
            for (int q = 0; q < 8; q++) {
                int sid = q * 32 + lane;
                int row = sid >> 4, c4 = (sid & 15) * 4;
                float4 bv = *(const float4*)(&bias[c0 + c4]);
                const float* er = epi + row * 68 + c4;
                float4 v;
                v.x = er[0] + bv.x; v.y = er[1] + bv.y;
                v.z = er[2] + bv.z; v.w = er[3] + bv.w;
                *(float4*)(&C[(size_t)(r0 + row) * NDIM + c0 + c4]) = v;
            }
        }
        __syncwarp();
    }
}

// ------------------------------- combine -------------------------------------
__global__ void combine_kernel(float* __restrict__ out) {
    int tok = blockIdx.x;
    int t   = threadIdx.x;
    int s1 = g_slot1[tok], s2 = g_slot2[tok];
    float g1 = (s1 >= 0) ? g_g1[tok] : 0.f;
    float g2 = (s2 >= 0) ? g_g2[tok] : 0.f;
    float4 v = make_float4(0.f, 0.f, 0.f, 0.f);
    if (s1 >= 0) {
        float4 a = ((const float4*)(g_eout + (size_t)s1 * DIMM))[t];
        v.x += g1 * a.x; v.y += g1 * a.y; v.z += g1 * a.z; v.w += g1 * a.w;
    }
    if (s2 >= 0) {
        float4 a = ((const float4*)(g_eout + (size_t)s2 * DIMM))[t];
        v.x += g2 * a.x; v.y += g2 * a.y; v.z += g2 * a.z; v.w += g2 * a.w;
    }
    ((float4*)(out + (size_t)tok * DIMM))[t] = v;
}

// -------------------------------- loss ---------------------------------------
__global__ void loss_part_kernel() {
    int be = blockIdx.x;
    int b = be / NE, e = be % NE;
    __shared__ float s[256];
    float acc = 0.f;
    for (int n = threadIdx.x; n < NN; n += 256)
        acc += g_probs[(size_t)(b * NN + n) * NE + e];
    s[threadIdx.x] = acc; __syncthreads();
    for (int off = 128; off; off >>= 1) {
        if (threadIdx.x < off) s[threadIdx.x] += s[threadIdx.x + off];
        __syncthreads();
    }
    if (threadIdx.x == 0)
        g_part_loss[be] = (s[0] / (float)NN) *
                          ((float)g_cnt_total[be] / (float)NN);
}

__global__ void loss_final_kernel(float* __restrict__ out) {
    __shared__ float s[64];
    int t = threadIdx.x;
    s[t] = g_part_loss[t]; __syncthreads();
    for (int off = 32; off; off >>= 1) {
        if (t < off) s[t] += s[t + off];
        __syncthreads();
    }
    if (t == 0) out[(size_t)NTOK * DIMM] = s[0] * 0.04f;
}

// ------------------------------- launch --------------------------------------
extern "C" void kernel_launch(void* const* d_in, const int* in_sizes, int n_in,
                              void* d_out, int out_size) {
    const float* x  = (const float*)d_in[0];
    const float* wg = (const float*)d_in[1];
    const float* w1 = (const float*)d_in[2];
    const float* w2 = (const float*)d_in[3];
    const float* b1 = (const float*)d_in[4];
    const float* b2 = (const float*)d_in[5];
    float* out = (float*)d_out;

    constexpr int SMEM = 4 * 18944;   // 75776
    cudaFuncSetAttribute(hgemm<DIMM, HID,  true >,
                         cudaFuncAttributeMaxDynamicSharedMemorySize, SMEM);
    cudaFuncSetAttribute(hgemm<HID,  DIMM, false>,
                         cudaFuncAttributeMaxDynamicSharedMemorySize, SMEM);

    const int W4 = NE * DIMM * HID / 4;     // 16.7M float4s per weight
    init_kernel<<<(NSLOT + 255) / 256, 256>>>();
    wconv_kernel<<<8192, 256>>>((const float4*)w1, 0, W4);
    wconv_kernel<<<8192, 256>>>((const float4*)w2, 1, W4);
    gating_kernel<<<NTOK / 16, 256>>>(x, wg);
    assign_kernel<<<BB * NE, 256>>>();
    gather_kernel<<<NSLOT, 256>>>(x);
    hgemm<DIMM, HID,  true ><<<dim3(HID  / 128, NSLOT / 128), 256, SMEM>>>(b1);
    hgemm<HID,  DIMM, false><<<dim3(DIMM / 128, NSLOT / 128), 256, SMEM>>>(b2);
    combine_kernel<<<NTOK, 256>>>(out);
    loss_part_kernel<<<BB * NE, 256>>>();
    if (out_size > NTOK * DIMM)
        loss_final_kernel<<<1, 64>>>(out);
}